// round 14
// baseline (speedup 1.0000x reference)
#include <cuda_runtime.h>

#define NN 50000
#define INF 128
#define HCC 128   // H*OUT
#define ED 64
#define EE 1600000

typedef unsigned long long u64;

// ---------------- scratch (device globals; no allocs allowed) ----------------
__device__ float4 d_qg[NN * 64];    // per node: q(128) | g(128)
__device__ float4 d_kv[NN * 64];    // per node: k(128) | v(128)
__device__ float4 d_acc[NN * 64];   // per node: vaccN(128) | taccN(128)  (normalized)
__device__ int    d_cnt[NN];
__device__ int    d_off[NN + 1];
__device__ int    d_pos[NN];
__device__ int    d_ssrc[EE];       // sorted-by-dst src
__device__ float4 d_sea[EE * 16];   // edge_attr materialized in sorted order (410MB)
__device__ float  d_Wt[HCC * HCC];  // block-diagonal [128][128] from We

// ---------------- packed fp32x2 helpers ----------------
__device__ __forceinline__ u64 bcast2(float v) {
    u64 r; asm("mov.b64 %0, {%1, %1};" : "=l"(r) : "f"(v)); return r;
}
__device__ __forceinline__ void fma2(u64& d, u64 a, u64 b) {
    asm("fma.rn.f32x2 %0, %1, %2, %0;" : "+l"(d) : "l"(a), "l"(b));
}
__device__ __forceinline__ float2 unpack2(u64 v) {
    float2 f; asm("mov.b64 {%0, %1}, %2;" : "=f"(f.x), "=f"(f.y) : "l"(v)); return f;
}

// ---------------- K0: zero histogram ----------------
__global__ void k0_zero() {
    int i = blockIdx.x * blockDim.x + threadIdx.x;
    if (i < NN) d_cnt[i] = 0;
}

// ---------------- sort pass 1: histogram of dst ----------------
__global__ void khist(const int* __restrict__ ei, int E) {
    int stride = gridDim.x * blockDim.x;
    for (int e = blockIdx.x * blockDim.x + threadIdx.x; e < E; e += stride)
        atomicAdd(&d_cnt[ei[E + e]], 1);
}

// ---------------- sort pass 2: exclusive scan (single CTA) ----------------
__global__ __launch_bounds__(1024) void kscan() {
    __shared__ int ssum[1024];
    const int T = 1024, per = (NN + T - 1) / T;
    int t = threadIdx.x;
    int base = t * per;
    int local = 0;
    for (int i = 0; i < per; i++) {
        int idx = base + i;
        if (idx < NN) local += d_cnt[idx];
    }
    ssum[t] = local;
    __syncthreads();
    for (int off = 1; off < T; off <<= 1) {
        int v = (t >= off) ? ssum[t - off] : 0;
        __syncthreads();
        ssum[t] += v;
        __syncthreads();
    }
    int run = ssum[t] - local;   // exclusive prefix
    for (int i = 0; i < per; i++) {
        int idx = base + i;
        if (idx < NN) {
            int c = d_cnt[idx];
            d_off[idx] = run;
            d_pos[idx] = run;
            run += c;
        }
    }
    if (t == T - 1) d_off[NN] = run;
}

// ---------------- sort pass 3: scatter src AND edge payload into sorted order ----------------
__global__ void kscatter(const int* __restrict__ ei, const float4* __restrict__ ea4, int E) {
    int stride = gridDim.x * blockDim.x;
    for (int e = blockIdx.x * blockDim.x + threadIdx.x; e < E; e += stride) {
        int dst = ei[E + e];
        int pos = atomicAdd(&d_pos[dst], 1);
        d_ssrc[pos] = ei[e];
        const float4* sp = ea4 + (long long)e * 16;
        float4* dp = d_sea + (long long)pos * 16;
#pragma unroll
        for (int i = 0; i < 16; i++) dp[i] = sp[i];
    }
}

// ---------------- KWT: build block-diagonal Wt[k][hc] from We[d][hc] ----------------
__global__ void kWt(const float* __restrict__ We) {
    int idx = blockIdx.x * 256 + threadIdx.x;   // 16384 total
    if (idx >= HCC * HCC) return;
    int k = idx >> 7, hc = idx & 127;
    d_Wt[idx] = ((k >> 6) == (hc >> 6)) ? We[(k & 63) * 128 + hc] : 0.f;
}

// ---------------- K1: C[N,512] = x[N,128] @ [Wq|Wk|Wv|Wskip] + bias ----------------
__global__ __launch_bounds__(256) void k1_gemm(
    const float* __restrict__ x,
    const float* __restrict__ Wq, const float* __restrict__ bq,
    const float* __restrict__ Wk, const float* __restrict__ bk,
    const float* __restrict__ Wv, const float* __restrict__ bv,
    const float* __restrict__ Wsk, const float* __restrict__ bsk,
    float* __restrict__ out, int n)
{
    __shared__ float As[8][128];
    __shared__ float Bs[8][128];

    const int t = threadIdx.x;
    const int m0 = blockIdx.x * 128;
    const int which = blockIdx.y;

    const float* W;
    const float* bias;
    if (which == 0)      { W = Wq;  bias = bq;  }
    else if (which == 1) { W = Wk;  bias = bk;  }
    else if (which == 2) { W = Wv;  bias = bv;  }
    else                 { W = Wsk; bias = bsk; }

    const int ty = t >> 4;
    const int tx = t & 15;

    u64 acc2[4][8];
#pragma unroll
    for (int i = 0; i < 4; i++)
#pragma unroll
        for (int j = 0; j < 8; j++) acc2[i][j] = 0ULL;

    const int lrow = t >> 1;
    const int lcg  = t & 1;
    const int brow = t >> 5;
    const int bc   = (t & 31) * 4;

    for (int k0 = 0; k0 < 128; k0 += 8) {
        float4 av = make_float4(0.f, 0.f, 0.f, 0.f);
        int gr = m0 + lrow;
        if (gr < n) av = *(const float4*)(x + (long long)gr * 128 + k0 + lcg * 4);
        float4 bv4 = *(const float4*)(W + (k0 + brow) * 128 + bc);

        __syncthreads();
        As[lcg * 4 + 0][lrow] = av.x;
        As[lcg * 4 + 1][lrow] = av.y;
        As[lcg * 4 + 2][lrow] = av.z;
        As[lcg * 4 + 3][lrow] = av.w;
        *(float4*)&Bs[brow][bc] = bv4;
        __syncthreads();

#pragma unroll
        for (int kk = 0; kk < 8; kk++) {
            ulonglong2 a01 = *(const ulonglong2*)&As[kk][ty * 8];
            ulonglong2 a23 = *(const ulonglong2*)&As[kk][ty * 8 + 4];
            u64 ra2[4] = { a01.x, a01.y, a23.x, a23.y };

            float rb[8];
            *(float4*)(rb)     = *(float4*)&Bs[kk][tx * 8];
            *(float4*)(rb + 4) = *(float4*)&Bs[kk][tx * 8 + 4];
            u64 rbb[8];
#pragma unroll
            for (int j = 0; j < 8; j++) rbb[j] = bcast2(rb[j]);

#pragma unroll
            for (int i2 = 0; i2 < 4; i2++)
#pragma unroll
                for (int j = 0; j < 8; j++) fma2(acc2[i2][j], ra2[i2], rbb[j]);
        }
    }

    float bb[8];
#pragma unroll
    for (int j = 0; j < 8; j++) bb[j] = bias[tx * 8 + j];

    const int colf4 = tx * 2;
#pragma unroll
    for (int i2 = 0; i2 < 4; i2++) {
        float lo[8], hi[8];
#pragma unroll
        for (int j = 0; j < 8; j++) {
            float2 f = unpack2(acc2[i2][j]);
            lo[j] = f.x + bb[j];
            hi[j] = f.y + bb[j];
        }
#pragma unroll
        for (int half = 0; half < 2; half++) {
            int row = m0 + ty * 8 + 2 * i2 + half;
            if (row >= n) continue;
            const float* v = half ? hi : lo;
            float4 o0 = make_float4(v[0], v[1], v[2], v[3]);
            float4 o1 = make_float4(v[4], v[5], v[6], v[7]);
            long long r = row;
            if (which == 0) {
                d_qg[r * 64 + colf4] = o0; d_qg[r * 64 + colf4 + 1] = o1;
            } else if (which == 1) {
                d_kv[r * 64 + colf4] = o0; d_kv[r * 64 + colf4 + 1] = o1;
            } else if (which == 2) {
                d_kv[r * 64 + 32 + colf4] = o0; d_kv[r * 64 + 32 + colf4 + 1] = o1;
            } else {
                ((float4*)out)[r * 32 + colf4] = o0;
                ((float4*)out)[r * 32 + colf4 + 1] = o1;
            }
        }
    }
}

// ---------------- K1b: g[i,h,d] = sum_c We[d][h*64+c] * q[i,h,c] ----------------
__global__ __launch_bounds__(256) void k_g(const float* __restrict__ We, int n)
{
    __shared__ float WeT[128][64];
    __shared__ float4 qs[16][32];

    const int t = threadIdx.x;
    const int base = blockIdx.x * 16;

    for (int idx = t; idx < 64 * 128; idx += 256) {
        int d = idx >> 7, k = idx & 127;
        WeT[k][d] = We[idx];
    }
#pragma unroll
    for (int r = 0; r < 2; r++) {
        int idx4 = t + r * 256;
        int nl = idx4 >> 5, c4 = idx4 & 31;
        int node = base + nl;
        qs[nl][c4] = (node < n) ? d_qg[(long long)node * 64 + c4]
                                : make_float4(0.f, 0.f, 0.f, 0.f);
    }
    __syncthreads();

    const int nl = t >> 4;
    const int og = t & 15;
    const int h = og >> 3;
    const int d0 = (og * 8) & 63;
    const float* qrow = (const float*)&qs[nl][0];

    float a0[4] = {0.f, 0.f, 0.f, 0.f};
    float a1[4] = {0.f, 0.f, 0.f, 0.f};
#pragma unroll
    for (int c = 0; c < 64; c++) {
        float qv = qrow[h * 64 + c];
        float4 w0 = *(float4*)&WeT[h * 64 + c][d0];
        float4 w1 = *(float4*)&WeT[h * 64 + c][d0 + 4];
        a0[0] += qv * w0.x; a0[1] += qv * w0.y; a0[2] += qv * w0.z; a0[3] += qv * w0.w;
        a1[0] += qv * w1.x; a1[1] += qv * w1.y; a1[2] += qv * w1.z; a1[3] += qv * w1.w;
    }
    int node = base + nl;
    if (node < n) {
        long long r = node;
        d_qg[r * 64 + 32 + og * 2]     = make_float4(a0[0], a0[1], a0[2], a0[3]);
        d_qg[r * 64 + 32 + og * 2 + 1] = make_float4(a1[0], a1[1], a1[2], a1[3]);
    }
}

// ---------------- K2: one warp per node; kv gather (L2) + SEQUENTIAL sorted ea ----------------
__global__ __launch_bounds__(256) void k2_nodes(int n)
{
    int node = (int)((blockIdx.x * 256u + threadIdx.x) >> 5);
    if (node >= n) return;
    const int lane = threadIdx.x & 31;
    const int li = lane & 15;

    const int start = d_off[node];
    const int end   = d_off[node + 1];

    const float4* qg = d_qg + (long long)node * 64;
    float4 q4 = qg[lane];
    float4 g4 = qg[32 + lane];

    float4 vac = make_float4(0.f, 0.f, 0.f, 0.f);
    float4 tac = make_float4(0.f, 0.f, 0.f, 0.f);
    float sw = 0.f;

    int j = start;
    if (j < end) {
        int src = d_ssrc[j];
        const float4* kvp = d_kv + (long long)src * 64;
        float4 kc = kvp[lane];
        float4 vc = kvp[32 + lane];
        float4 ec = __ldcs(d_sea + (long long)j * 16 + li);

        for (; j < end; j++) {
            int jn = (j + 1 < end) ? j + 1 : j;
            int srcn = d_ssrc[jn];
            const float4* kvn = d_kv + (long long)srcn * 64;
            float4 kn = kvn[lane];
            float4 vn = kvn[32 + lane];
            float4 en = __ldcs(d_sea + (long long)jn * 16 + li);

            float p = q4.x * kc.x + q4.y * kc.y + q4.z * kc.z + q4.w * kc.w
                    + ec.x * g4.x + ec.y * g4.y + ec.z * g4.z + ec.w * g4.w;

            p += __shfl_xor_sync(0xffffffffu, p, 8);
            p += __shfl_xor_sync(0xffffffffu, p, 4);
            p += __shfl_xor_sync(0xffffffffu, p, 2);
            p += __shfl_xor_sync(0xffffffffu, p, 1);

            float w = __expf(p * 0.125f);   // 1/sqrt(64)
            sw += w;
            vac.x += w * vc.x; vac.y += w * vc.y; vac.z += w * vc.z; vac.w += w * vc.w;
            tac.x += w * ec.x; tac.y += w * ec.y; tac.z += w * ec.z; tac.w += w * ec.w;

            kc = kn; vc = vn; ec = en;
        }
    }

    // normalize in-register (softmax denominator); per-16-lane group sum == per-head sum
    float inv = 1.f / (sw + 1e-16f);
    vac.x *= inv; vac.y *= inv; vac.z *= inv; vac.w *= inv;
    tac.x *= inv; tac.y *= inv; tac.z *= inv; tac.w *= inv;

    float4* accp = d_acc + (long long)node * 64;
    accp[lane]      = vac;
    accp[32 + lane] = tac;
}

// ---------------- K3: out += vaccN + taccN @ Wt  (GEMM, same tiling as K1) ----------------
__global__ __launch_bounds__(256) void k3_gemm(float* __restrict__ out, int n)
{
    __shared__ float As[8][128];
    __shared__ float Bs[8][128];

    const int t = threadIdx.x;
    const int m0 = blockIdx.x * 128;

    const int ty = t >> 4;
    const int tx = t & 15;

    u64 acc2[4][8];
#pragma unroll
    for (int i = 0; i < 4; i++)
#pragma unroll
        for (int j = 0; j < 8; j++) acc2[i][j] = 0ULL;

    const int lrow = t >> 1;
    const int lcg  = t & 1;
    const int brow = t >> 5;
    const int bc   = (t & 31) * 4;

    for (int k0 = 0; k0 < 128; k0 += 8) {
        float4 av = make_float4(0.f, 0.f, 0.f, 0.f);
        int gr = m0 + lrow;
        if (gr < n) av = d_acc[(long long)gr * 64 + 32 + (k0 >> 2) + lcg];
        float4 bv4 = *(const float4*)(d_Wt + (k0 + brow) * 128 + bc);

        __syncthreads();
        As[lcg * 4 + 0][lrow] = av.x;
        As[lcg * 4 + 1][lrow] = av.y;
        As[lcg * 4 + 2][lrow] = av.z;
        As[lcg * 4 + 3][lrow] = av.w;
        *(float4*)&Bs[brow][bc] = bv4;
        __syncthreads();

#pragma unroll
        for (int kk = 0; kk < 8; kk++) {
            ulonglong2 a01 = *(const ulonglong2*)&As[kk][ty * 8];
            ulonglong2 a23 = *(const ulonglong2*)&As[kk][ty * 8 + 4];
            u64 ra2[4] = { a01.x, a01.y, a23.x, a23.y };

            float rb[8];
            *(float4*)(rb)     = *(float4*)&Bs[kk][tx * 8];
            *(float4*)(rb + 4) = *(float4*)&Bs[kk][tx * 8 + 4];
            u64 rbb[8];
#pragma unroll
            for (int j = 0; j < 8; j++) rbb[j] = bcast2(rb[j]);

#pragma unroll
            for (int i2 = 0; i2 < 4; i2++)
#pragma unroll
                for (int j = 0; j < 8; j++) fma2(acc2[i2][j], ra2[i2], rbb[j]);
        }
    }

    const int colf4 = tx * 2;
#pragma unroll
    for (int i2 = 0; i2 < 4; i2++) {
        float lo[8], hi[8];
#pragma unroll
        for (int j = 0; j < 8; j++) {
            float2 f = unpack2(acc2[i2][j]);
            lo[j] = f.x;
            hi[j] = f.y;
        }
#pragma unroll
        for (int half = 0; half < 2; half++) {
            int row = m0 + ty * 8 + 2 * i2 + half;
            if (row >= n) continue;
            const float* v = half ? hi : lo;
            long long r = row;
            float4 va0 = d_acc[r * 64 + colf4];
            float4 va1 = d_acc[r * 64 + colf4 + 1];
            float4 o0 = ((float4*)out)[r * 32 + colf4];
            float4 o1 = ((float4*)out)[r * 32 + colf4 + 1];
            o0.x += va0.x + v[0]; o0.y += va0.y + v[1];
            o0.z += va0.z + v[2]; o0.w += va0.w + v[3];
            o1.x += va1.x + v[4]; o1.y += va1.y + v[5];
            o1.z += va1.z + v[6]; o1.w += va1.w + v[7];
            ((float4*)out)[r * 32 + colf4]     = o0;
            ((float4*)out)[r * 32 + colf4 + 1] = o1;
        }
    }
}

// ---------------- launch ----------------
extern "C" void kernel_launch(void* const* d_in, const int* in_sizes, int n_in,
                              void* d_out, int out_size)
{
    const float* x   = (const float*)d_in[0];
    const int*   ei  = (const int*)d_in[1];     // int32 (JAX x64 disabled)
    const float* ea  = (const float*)d_in[2];
    const float* Wq  = (const float*)d_in[3];
    const float* bq  = (const float*)d_in[4];
    const float* Wk  = (const float*)d_in[5];
    const float* bk  = (const float*)d_in[6];
    const float* Wv  = (const float*)d_in[7];
    const float* bv  = (const float*)d_in[8];
    const float* We  = (const float*)d_in[9];
    const float* Wsk = (const float*)d_in[10];
    const float* bsk = (const float*)d_in[11];

    int n = in_sizes[0] / INF;        // 50000
    int E = in_sizes[2] / ED;         // 1600000
    float* out = (float*)d_out;

    k0_zero<<<(NN + 255) / 256, 256>>>();                        // launch 1
    khist<<<1184, 256>>>(ei, E);                                 // launch 2
    kscan<<<1, 1024>>>();                                        // launch 3
    kscatter<<<1184, 256>>>(ei, (const float4*)ea, E);           // launch 4 (ncu slot)
    kWt<<<(HCC * HCC + 255) / 256, 256>>>(We);                   // launch 5

    dim3 g1((n + 127) / 128, 4);
    k1_gemm<<<g1, 256>>>(x, Wq, bq, Wk, bk, Wv, bv, Wsk, bsk, out, n);  // launch 6

    k_g<<<(n + 15) / 16, 256>>>(We, n);                          // launch 7
    k2_nodes<<<(n * 32 + 255) / 256, 256>>>(n);                  // launch 8
    k3_gemm<<<(n + 127) / 128, 256>>>(out, n);                   // launch 9
}

// round 15
// speedup vs baseline: 1.4915x; 1.4915x over previous
#include <cuda_runtime.h>

#define NN 50000
#define INF 128
#define HCC 128   // H*OUT
#define ED 64
#define EE 1600000

typedef unsigned long long u64;

// ---------------- scratch (device globals; no allocs allowed) ----------------
__device__ float4 d_qg[NN * 64];    // per node: q(128) | g(128)
__device__ float4 d_kv[NN * 64];    // per node: k(128) | v(128)
__device__ float4 d_acc[NN * 64];   // per node: vaccN(128) | taccN(128)  (normalized)
__device__ int    d_cnt[NN];
__device__ int    d_off[NN + 1];
__device__ int    d_pos[NN];
__device__ int2   d_sed[EE];        // sorted-by-dst (src, edge_id)
__device__ float  d_Wt[HCC * HCC];  // block-diagonal [128][128] from We

// ---------------- packed fp32x2 helpers ----------------
__device__ __forceinline__ u64 bcast2(float v) {
    u64 r; asm("mov.b64 %0, {%1, %1};" : "=l"(r) : "f"(v)); return r;
}
__device__ __forceinline__ void fma2(u64& d, u64 a, u64 b) {
    asm("fma.rn.f32x2 %0, %1, %2, %0;" : "+l"(d) : "l"(a), "l"(b));
}
__device__ __forceinline__ float2 unpack2(u64 v) {
    float2 f; asm("mov.b64 {%0, %1}, %2;" : "=f"(f.x), "=f"(f.y) : "l"(v)); return f;
}

// ---------------- K0: zero histogram ----------------
__global__ void k0_zero() {
    int i = blockIdx.x * blockDim.x + threadIdx.x;
    if (i < NN) d_cnt[i] = 0;
}

// ---------------- sort pass 1: histogram of dst ----------------
__global__ void khist(const int* __restrict__ ei, int E) {
    int stride = gridDim.x * blockDim.x;
    for (int e = blockIdx.x * blockDim.x + threadIdx.x; e < E; e += stride)
        atomicAdd(&d_cnt[ei[E + e]], 1);
}

// ---------------- sort pass 2: exclusive scan (single CTA) ----------------
__global__ __launch_bounds__(1024) void kscan() {
    __shared__ int ssum[1024];
    const int T = 1024, per = (NN + T - 1) / T;
    int t = threadIdx.x;
    int base = t * per;
    int local = 0;
    for (int i = 0; i < per; i++) {
        int idx = base + i;
        if (idx < NN) local += d_cnt[idx];
    }
    ssum[t] = local;
    __syncthreads();
    for (int off = 1; off < T; off <<= 1) {
        int v = (t >= off) ? ssum[t - off] : 0;
        __syncthreads();
        ssum[t] += v;
        __syncthreads();
    }
    int run = ssum[t] - local;   // exclusive prefix
    for (int i = 0; i < per; i++) {
        int idx = base + i;
        if (idx < NN) {
            int c = d_cnt[idx];
            d_off[idx] = run;
            d_pos[idx] = run;
            run += c;
        }
    }
    if (t == T - 1) d_off[NN] = run;
}

// ---------------- sort pass 3: scatter (src, eid) into dst-sorted order ----------------
__global__ void kscatter(const int* __restrict__ ei, int E) {
    int stride = gridDim.x * blockDim.x;
    for (int e = blockIdx.x * blockDim.x + threadIdx.x; e < E; e += stride) {
        int dst = ei[E + e];
        int pos = atomicAdd(&d_pos[dst], 1);
        d_sed[pos] = make_int2(ei[e], e);
    }
}

// ---------------- KWT: build block-diagonal Wt[k][hc] from We[d][hc] ----------------
__global__ void kWt(const float* __restrict__ We) {
    int idx = blockIdx.x * 256 + threadIdx.x;   // 16384 total
    if (idx >= HCC * HCC) return;
    int k = idx >> 7, hc = idx & 127;
    d_Wt[idx] = ((k >> 6) == (hc >> 6)) ? We[(k & 63) * 128 + hc] : 0.f;
}

// ---------------- K1: C[N,512] = x[N,128] @ [Wq|Wk|Wv|Wskip] + bias ----------------
__global__ __launch_bounds__(256) void k1_gemm(
    const float* __restrict__ x,
    const float* __restrict__ Wq, const float* __restrict__ bq,
    const float* __restrict__ Wk, const float* __restrict__ bk,
    const float* __restrict__ Wv, const float* __restrict__ bv,
    const float* __restrict__ Wsk, const float* __restrict__ bsk,
    float* __restrict__ out, int n)
{
    __shared__ float As[8][128];
    __shared__ float Bs[8][128];

    const int t = threadIdx.x;
    const int m0 = blockIdx.x * 128;
    const int which = blockIdx.y;

    const float* W;
    const float* bias;
    if (which == 0)      { W = Wq;  bias = bq;  }
    else if (which == 1) { W = Wk;  bias = bk;  }
    else if (which == 2) { W = Wv;  bias = bv;  }
    else                 { W = Wsk; bias = bsk; }

    const int ty = t >> 4;
    const int tx = t & 15;

    u64 acc2[4][8];
#pragma unroll
    for (int i = 0; i < 4; i++)
#pragma unroll
        for (int j = 0; j < 8; j++) acc2[i][j] = 0ULL;

    const int lrow = t >> 1;
    const int lcg  = t & 1;
    const int brow = t >> 5;
    const int bc   = (t & 31) * 4;

    for (int k0 = 0; k0 < 128; k0 += 8) {
        float4 av = make_float4(0.f, 0.f, 0.f, 0.f);
        int gr = m0 + lrow;
        if (gr < n) av = *(const float4*)(x + (long long)gr * 128 + k0 + lcg * 4);
        float4 bv4 = *(const float4*)(W + (k0 + brow) * 128 + bc);

        __syncthreads();
        As[lcg * 4 + 0][lrow] = av.x;
        As[lcg * 4 + 1][lrow] = av.y;
        As[lcg * 4 + 2][lrow] = av.z;
        As[lcg * 4 + 3][lrow] = av.w;
        *(float4*)&Bs[brow][bc] = bv4;
        __syncthreads();

#pragma unroll
        for (int kk = 0; kk < 8; kk++) {
            ulonglong2 a01 = *(const ulonglong2*)&As[kk][ty * 8];
            ulonglong2 a23 = *(const ulonglong2*)&As[kk][ty * 8 + 4];
            u64 ra2[4] = { a01.x, a01.y, a23.x, a23.y };

            float rb[8];
            *(float4*)(rb)     = *(float4*)&Bs[kk][tx * 8];
            *(float4*)(rb + 4) = *(float4*)&Bs[kk][tx * 8 + 4];
            u64 rbb[8];
#pragma unroll
            for (int j = 0; j < 8; j++) rbb[j] = bcast2(rb[j]);

#pragma unroll
            for (int i2 = 0; i2 < 4; i2++)
#pragma unroll
                for (int j = 0; j < 8; j++) fma2(acc2[i2][j], ra2[i2], rbb[j]);
        }
    }

    float bb[8];
#pragma unroll
    for (int j = 0; j < 8; j++) bb[j] = bias[tx * 8 + j];

    const int colf4 = tx * 2;
#pragma unroll
    for (int i2 = 0; i2 < 4; i2++) {
        float lo[8], hi[8];
#pragma unroll
        for (int j = 0; j < 8; j++) {
            float2 f = unpack2(acc2[i2][j]);
            lo[j] = f.x + bb[j];
            hi[j] = f.y + bb[j];
        }
#pragma unroll
        for (int half = 0; half < 2; half++) {
            int row = m0 + ty * 8 + 2 * i2 + half;
            if (row >= n) continue;
            const float* v = half ? hi : lo;
            float4 o0 = make_float4(v[0], v[1], v[2], v[3]);
            float4 o1 = make_float4(v[4], v[5], v[6], v[7]);
            long long r = row;
            if (which == 0) {
                d_qg[r * 64 + colf4] = o0; d_qg[r * 64 + colf4 + 1] = o1;
            } else if (which == 1) {
                d_kv[r * 64 + colf4] = o0; d_kv[r * 64 + colf4 + 1] = o1;
            } else if (which == 2) {
                d_kv[r * 64 + 32 + colf4] = o0; d_kv[r * 64 + 32 + colf4 + 1] = o1;
            } else {
                ((float4*)out)[r * 32 + colf4] = o0;
                ((float4*)out)[r * 32 + colf4 + 1] = o1;
            }
        }
    }
}

// ---------------- K1b: g[i,h,d] = sum_c We[d][h*64+c] * q[i,h,c] ----------------
__global__ __launch_bounds__(256) void k_g(const float* __restrict__ We, int n)
{
    __shared__ float WeT[128][64];
    __shared__ float4 qs[16][32];

    const int t = threadIdx.x;
    const int base = blockIdx.x * 16;

    for (int idx = t; idx < 64 * 128; idx += 256) {
        int d = idx >> 7, k = idx & 127;
        WeT[k][d] = We[idx];
    }
#pragma unroll
    for (int r = 0; r < 2; r++) {
        int idx4 = t + r * 256;
        int nl = idx4 >> 5, c4 = idx4 & 31;
        int node = base + nl;
        qs[nl][c4] = (node < n) ? d_qg[(long long)node * 64 + c4]
                                : make_float4(0.f, 0.f, 0.f, 0.f);
    }
    __syncthreads();

    const int nl = t >> 4;
    const int og = t & 15;
    const int h = og >> 3;
    const int d0 = (og * 8) & 63;
    const float* qrow = (const float*)&qs[nl][0];

    float a0[4] = {0.f, 0.f, 0.f, 0.f};
    float a1[4] = {0.f, 0.f, 0.f, 0.f};
#pragma unroll
    for (int c = 0; c < 64; c++) {
        float qv = qrow[h * 64 + c];
        float4 w0 = *(float4*)&WeT[h * 64 + c][d0];
        float4 w1 = *(float4*)&WeT[h * 64 + c][d0 + 4];
        a0[0] += qv * w0.x; a0[1] += qv * w0.y; a0[2] += qv * w0.z; a0[3] += qv * w0.w;
        a1[0] += qv * w1.x; a1[1] += qv * w1.y; a1[2] += qv * w1.z; a1[3] += qv * w1.w;
    }
    int node = base + nl;
    if (node < n) {
        long long r = node;
        d_qg[r * 64 + 32 + og * 2]     = make_float4(a0[0], a0[1], a0[2], a0[3]);
        d_qg[r * 64 + 32 + og * 2 + 1] = make_float4(a1[0], a1[1], a1[2], a1[3]);
    }
}

// ---------------- K2: one warp per node, depth-2 prefetch, __ldcs ea gather ----------------
__global__ __launch_bounds__(256) void k2_nodes(const float* __restrict__ ea, int n)
{
    int node = (int)((blockIdx.x * 256u + threadIdx.x) >> 5);
    if (node >= n) return;
    const int lane = threadIdx.x & 31;
    const int li = lane & 15;

    const int start = d_off[node];
    const int end   = d_off[node + 1];

    const float4* qg = d_qg + (long long)node * 64;
    float4 q4 = qg[lane];
    float4 g4 = qg[32 + lane];

    float4 vac = make_float4(0.f, 0.f, 0.f, 0.f);
    float4 tac = make_float4(0.f, 0.f, 0.f, 0.f);
    float sw = 0.f;

    for (int j0 = start; j0 < end; j0 += 32) {
        int nb = end - j0; if (nb > 32) nb = 32;
        int2 se = (lane < nb) ? d_sed[j0 + lane] : make_int2(0, 0);

        // prefetch edge 0
        int src = __shfl_sync(0xffffffffu, se.x, 0);
        int eid = __shfl_sync(0xffffffffu, se.y, 0);
        const float4* kvp = d_kv + (long long)src * 64;
        float4 kc = kvp[lane];
        float4 vc = kvp[32 + lane];
        float4 ec = __ldcs(((const float4*)ea) + (long long)eid * 16 + li);

        for (int jj = 0; jj < nb; jj++) {
            int jn = (jj + 1 < nb) ? (jj + 1) : jj;
            int srcn = __shfl_sync(0xffffffffu, se.x, jn);
            int eidn = __shfl_sync(0xffffffffu, se.y, jn);
            const float4* kvn = d_kv + (long long)srcn * 64;
            float4 kn = kvn[lane];
            float4 vn = kvn[32 + lane];
            float4 en = __ldcs(((const float4*)ea) + (long long)eidn * 16 + li);

            float p = q4.x * kc.x + q4.y * kc.y + q4.z * kc.z + q4.w * kc.w
                    + ec.x * g4.x + ec.y * g4.y + ec.z * g4.z + ec.w * g4.w;

            p += __shfl_xor_sync(0xffffffffu, p, 8);
            p += __shfl_xor_sync(0xffffffffu, p, 4);
            p += __shfl_xor_sync(0xffffffffu, p, 2);
            p += __shfl_xor_sync(0xffffffffu, p, 1);

            float w = __expf(p * 0.125f);   // 1/sqrt(64)
            sw += w;
            vac.x += w * vc.x; vac.y += w * vc.y; vac.z += w * vc.z; vac.w += w * vc.w;
            tac.x += w * ec.x; tac.y += w * ec.y; tac.z += w * ec.z; tac.w += w * ec.w;

            kc = kn; vc = vn; ec = en;
        }
    }

    // normalize in-register (per-warp sw is per-node total; same for both heads' lanes)
    float inv = 1.f / (sw + 1e-16f);
    vac.x *= inv; vac.y *= inv; vac.z *= inv; vac.w *= inv;
    tac.x *= inv; tac.y *= inv; tac.z *= inv; tac.w *= inv;

    float4* accp = d_acc + (long long)node * 64;
    accp[lane]      = vac;
    accp[32 + lane] = tac;
}

// ---------------- K3: out += vaccN + taccN @ Wt  (GEMM, same tiling as K1) ----------------
__global__ __launch_bounds__(256) void k3_gemm(float* __restrict__ out, int n)
{
    __shared__ float As[8][128];
    __shared__ float Bs[8][128];

    const int t = threadIdx.x;
    const int m0 = blockIdx.x * 128;

    const int ty = t >> 4;
    const int tx = t & 15;

    u64 acc2[4][8];
#pragma unroll
    for (int i = 0; i < 4; i++)
#pragma unroll
        for (int j = 0; j < 8; j++) acc2[i][j] = 0ULL;

    const int lrow = t >> 1;
    const int lcg  = t & 1;
    const int brow = t >> 5;
    const int bc   = (t & 31) * 4;

    for (int k0 = 0; k0 < 128; k0 += 8) {
        float4 av = make_float4(0.f, 0.f, 0.f, 0.f);
        int gr = m0 + lrow;
        if (gr < n) av = d_acc[(long long)gr * 64 + 32 + (k0 >> 2) + lcg];
        float4 bv4 = *(const float4*)(d_Wt + (k0 + brow) * 128 + bc);

        __syncthreads();
        As[lcg * 4 + 0][lrow] = av.x;
        As[lcg * 4 + 1][lrow] = av.y;
        As[lcg * 4 + 2][lrow] = av.z;
        As[lcg * 4 + 3][lrow] = av.w;
        *(float4*)&Bs[brow][bc] = bv4;
        __syncthreads();

#pragma unroll
        for (int kk = 0; kk < 8; kk++) {
            ulonglong2 a01 = *(const ulonglong2*)&As[kk][ty * 8];
            ulonglong2 a23 = *(const ulonglong2*)&As[kk][ty * 8 + 4];
            u64 ra2[4] = { a01.x, a01.y, a23.x, a23.y };

            float rb[8];
            *(float4*)(rb)     = *(float4*)&Bs[kk][tx * 8];
            *(float4*)(rb + 4) = *(float4*)&Bs[kk][tx * 8 + 4];
            u64 rbb[8];
#pragma unroll
            for (int j = 0; j < 8; j++) rbb[j] = bcast2(rb[j]);

#pragma unroll
            for (int i2 = 0; i2 < 4; i2++)
#pragma unroll
                for (int j = 0; j < 8; j++) fma2(acc2[i2][j], ra2[i2], rbb[j]);
        }
    }

    const int colf4 = tx * 2;
#pragma unroll
    for (int i2 = 0; i2 < 4; i2++) {
        float lo[8], hi[8];
#pragma unroll
        for (int j = 0; j < 8; j++) {
            float2 f = unpack2(acc2[i2][j]);
            lo[j] = f.x;
            hi[j] = f.y;
        }
#pragma unroll
        for (int half = 0; half < 2; half++) {
            int row = m0 + ty * 8 + 2 * i2 + half;
            if (row >= n) continue;
            const float* v = half ? hi : lo;
            long long r = row;
            float4 va0 = d_acc[r * 64 + colf4];
            float4 va1 = d_acc[r * 64 + colf4 + 1];
            float4 o0 = ((float4*)out)[r * 32 + colf4];
            float4 o1 = ((float4*)out)[r * 32 + colf4 + 1];
            o0.x += va0.x + v[0]; o0.y += va0.y + v[1];
            o0.z += va0.z + v[2]; o0.w += va0.w + v[3];
            o1.x += va1.x + v[4]; o1.y += va1.y + v[5];
            o1.z += va1.z + v[6]; o1.w += va1.w + v[7];
            ((float4*)out)[r * 32 + colf4]     = o0;
            ((float4*)out)[r * 32 + colf4 + 1] = o1;
        }
    }
}

// ---------------- launch ----------------
extern "C" void kernel_launch(void* const* d_in, const int* in_sizes, int n_in,
                              void* d_out, int out_size)
{
    const float* x   = (const float*)d_in[0];
    const int*   ei  = (const int*)d_in[1];     // int32 (JAX x64 disabled)
    const float* ea  = (const float*)d_in[2];
    const float* Wq  = (const float*)d_in[3];
    const float* bq  = (const float*)d_in[4];
    const float* Wk  = (const float*)d_in[5];
    const float* bk  = (const float*)d_in[6];
    const float* Wv  = (const float*)d_in[7];
    const float* bv  = (const float*)d_in[8];
    const float* We  = (const float*)d_in[9];
    const float* Wsk = (const float*)d_in[10];
    const float* bsk = (const float*)d_in[11];

    int n = in_sizes[0] / INF;        // 50000
    int E = in_sizes[2] / ED;         // 1600000
    float* out = (float*)d_out;

    dim3 g1((n + 127) / 128, 4);
    k1_gemm<<<g1, 256>>>(x, Wq, bq, Wk, bk, Wv, bv, Wsk, bsk, out, n);  // launch 1
    k0_zero<<<(NN + 255) / 256, 256>>>();                               // launch 2
    khist<<<1184, 256>>>(ei, E);                                        // launch 3
    k_g<<<(n + 15) / 16, 256>>>(We, n);                                 // launch 4 (ncu slot)
    kscan<<<1, 1024>>>();                                               // launch 5
    kscatter<<<1184, 256>>>(ei, E);                                     // launch 6
    kWt<<<(HCC * HCC + 255) / 256, 256>>>(We);                          // launch 7
    k2_nodes<<<(n * 32 + 255) / 256, 256>>>(ea, n);                     // launch 8
    k3_gemm<<<(n + 127) / 128, 256>>>(out, n);                          // launch 9
}

// round 16
// speedup vs baseline: 1.7729x; 1.1887x over previous
#include <cuda_runtime.h>

#define NN 50000
#define INF 128
#define HCC 128   // H*OUT
#define ED 64
#define EE 1600000

typedef unsigned long long u64;

// ---------------- scratch (device globals; no allocs allowed) ----------------
__device__ float4 d_qg[NN * 64];    // per node: q(128) | g(128)
__device__ float4 d_kv[NN * 64];    // per node: k(128) | v(128)
__device__ float4 d_acc[NN * 64];   // per node: vaccN(128) | taccN(128)  (normalized)
__device__ int    d_cnt[NN];
__device__ int    d_off[NN + 1];
__device__ int    d_pos[NN];
__device__ int2   d_sed[EE];        // sorted-by-dst (src, edge_id)
__device__ float  d_Wt[HCC * HCC];  // block-diag [k=h,d][hc]   (for k3: tacc @ We)
__device__ float  d_Wg[HCC * HCC];  // block-diag [k=h,c][h,d]  (for kg: q @ We^T)

// ---------------- packed fp32x2 helpers ----------------
__device__ __forceinline__ u64 bcast2(float v) {
    u64 r; asm("mov.b64 %0, {%1, %1};" : "=l"(r) : "f"(v)); return r;
}
__device__ __forceinline__ void fma2(u64& d, u64 a, u64 b) {
    asm("fma.rn.f32x2 %0, %1, %2, %0;" : "+l"(d) : "l"(a), "l"(b));
}
__device__ __forceinline__ float2 unpack2(u64 v) {
    float2 f; asm("mov.b64 {%0, %1}, %2;" : "=f"(f.x), "=f"(f.y) : "l"(v)); return f;
}

// ---------------- K0: zero histogram ----------------
__global__ void k0_zero() {
    int i = blockIdx.x * blockDim.x + threadIdx.x;
    if (i < NN) d_cnt[i] = 0;
}

// ---------------- sort pass 1: histogram of dst ----------------
__global__ void khist(const int* __restrict__ ei, int E) {
    int stride = gridDim.x * blockDim.x;
    for (int e = blockIdx.x * blockDim.x + threadIdx.x; e < E; e += stride)
        atomicAdd(&d_cnt[ei[E + e]], 1);
}

// ---------------- sort pass 2: exclusive scan (single CTA) ----------------
__global__ __launch_bounds__(1024) void kscan() {
    __shared__ int ssum[1024];
    const int T = 1024, per = (NN + T - 1) / T;
    int t = threadIdx.x;
    int base = t * per;
    int local = 0;
    for (int i = 0; i < per; i++) {
        int idx = base + i;
        if (idx < NN) local += d_cnt[idx];
    }
    ssum[t] = local;
    __syncthreads();
    for (int off = 1; off < T; off <<= 1) {
        int v = (t >= off) ? ssum[t - off] : 0;
        __syncthreads();
        ssum[t] += v;
        __syncthreads();
    }
    int run = ssum[t] - local;   // exclusive prefix
    for (int i = 0; i < per; i++) {
        int idx = base + i;
        if (idx < NN) {
            int c = d_cnt[idx];
            d_off[idx] = run;
            d_pos[idx] = run;
            run += c;
        }
    }
    if (t == T - 1) d_off[NN] = run;
}

// ---------------- sort pass 3: scatter (src, eid) into dst-sorted order ----------------
__global__ void kscatter(const int* __restrict__ ei, int E) {
    int stride = gridDim.x * blockDim.x;
    for (int e = blockIdx.x * blockDim.x + threadIdx.x; e < E; e += stride) {
        int dst = ei[E + e];
        int pos = atomicAdd(&d_pos[dst], 1);
        d_sed[pos] = make_int2(ei[e], e);
    }
}

// ---------------- KWT: Wt[k][hc] = We[k&63][hc] on diag blocks (k3 weight) ----------------
__global__ void kWt(const float* __restrict__ We) {
    int idx = blockIdx.x * 256 + threadIdx.x;   // 16384 total
    if (idx >= HCC * HCC) return;
    int k = idx >> 7, hc = idx & 127;
    d_Wt[idx] = ((k >> 6) == (hc >> 6)) ? We[(k & 63) * 128 + hc] : 0.f;
}

// ---------------- KWG: Wg[k=h*64+c][j=h*64+d] = We[d][h*64+c] on diag blocks ----------------
__global__ void kWg(const float* __restrict__ We) {
    int idx = blockIdx.x * 256 + threadIdx.x;   // 16384 total
    if (idx >= HCC * HCC) return;
    int k = idx >> 7, j = idx & 127;
    d_Wg[idx] = ((k >> 6) == (j >> 6)) ? We[(j & 63) * 128 + k] : 0.f;
}

// ---------------- K1: C[N,512] = x[N,128] @ [Wq|Wk|Wv|Wskip] + bias ----------------
__global__ __launch_bounds__(256) void k1_gemm(
    const float* __restrict__ x,
    const float* __restrict__ Wq, const float* __restrict__ bq,
    const float* __restrict__ Wk, const float* __restrict__ bk,
    const float* __restrict__ Wv, const float* __restrict__ bv,
    const float* __restrict__ Wsk, const float* __restrict__ bsk,
    float* __restrict__ out, int n)
{
    __shared__ float As[8][128];
    __shared__ float Bs[8][128];

    const int t = threadIdx.x;
    const int m0 = blockIdx.x * 128;
    const int which = blockIdx.y;

    const float* W;
    const float* bias;
    if (which == 0)      { W = Wq;  bias = bq;  }
    else if (which == 1) { W = Wk;  bias = bk;  }
    else if (which == 2) { W = Wv;  bias = bv;  }
    else                 { W = Wsk; bias = bsk; }

    const int ty = t >> 4;
    const int tx = t & 15;

    u64 acc2[4][8];
#pragma unroll
    for (int i = 0; i < 4; i++)
#pragma unroll
        for (int j = 0; j < 8; j++) acc2[i][j] = 0ULL;

    const int lrow = t >> 1;
    const int lcg  = t & 1;
    const int brow = t >> 5;
    const int bc   = (t & 31) * 4;

    for (int k0 = 0; k0 < 128; k0 += 8) {
        float4 av = make_float4(0.f, 0.f, 0.f, 0.f);
        int gr = m0 + lrow;
        if (gr < n) av = *(const float4*)(x + (long long)gr * 128 + k0 + lcg * 4);
        float4 bv4 = *(const float4*)(W + (k0 + brow) * 128 + bc);

        __syncthreads();
        As[lcg * 4 + 0][lrow] = av.x;
        As[lcg * 4 + 1][lrow] = av.y;
        As[lcg * 4 + 2][lrow] = av.z;
        As[lcg * 4 + 3][lrow] = av.w;
        *(float4*)&Bs[brow][bc] = bv4;
        __syncthreads();

#pragma unroll
        for (int kk = 0; kk < 8; kk++) {
            ulonglong2 a01 = *(const ulonglong2*)&As[kk][ty * 8];
            ulonglong2 a23 = *(const ulonglong2*)&As[kk][ty * 8 + 4];
            u64 ra2[4] = { a01.x, a01.y, a23.x, a23.y };

            float rb[8];
            *(float4*)(rb)     = *(float4*)&Bs[kk][tx * 8];
            *(float4*)(rb + 4) = *(float4*)&Bs[kk][tx * 8 + 4];
            u64 rbb[8];
#pragma unroll
            for (int j = 0; j < 8; j++) rbb[j] = bcast2(rb[j]);

#pragma unroll
            for (int i2 = 0; i2 < 4; i2++)
#pragma unroll
                for (int j = 0; j < 8; j++) fma2(acc2[i2][j], ra2[i2], rbb[j]);
        }
    }

    float bb[8];
#pragma unroll
    for (int j = 0; j < 8; j++) bb[j] = bias[tx * 8 + j];

    const int colf4 = tx * 2;
#pragma unroll
    for (int i2 = 0; i2 < 4; i2++) {
        float lo[8], hi[8];
#pragma unroll
        for (int j = 0; j < 8; j++) {
            float2 f = unpack2(acc2[i2][j]);
            lo[j] = f.x + bb[j];
            hi[j] = f.y + bb[j];
        }
#pragma unroll
        for (int half = 0; half < 2; half++) {
            int row = m0 + ty * 8 + 2 * i2 + half;
            if (row >= n) continue;
            const float* v = half ? hi : lo;
            float4 o0 = make_float4(v[0], v[1], v[2], v[3]);
            float4 o1 = make_float4(v[4], v[5], v[6], v[7]);
            long long r = row;
            if (which == 0) {
                d_qg[r * 64 + colf4] = o0; d_qg[r * 64 + colf4 + 1] = o1;
            } else if (which == 1) {
                d_kv[r * 64 + colf4] = o0; d_kv[r * 64 + colf4 + 1] = o1;
            } else if (which == 2) {
                d_kv[r * 64 + 32 + colf4] = o0; d_kv[r * 64 + 32 + colf4 + 1] = o1;
            } else {
                ((float4*)out)[r * 32 + colf4] = o0;
                ((float4*)out)[r * 32 + colf4 + 1] = o1;
            }
        }
    }
}

// ---------------- KG: g = q @ Wg  (GEMM, writes d_qg[:,32:]) ----------------
__global__ __launch_bounds__(256) void kg_gemm(int n)
{
    __shared__ float As[8][128];
    __shared__ float Bs[8][128];

    const int t = threadIdx.x;
    const int m0 = blockIdx.x * 128;

    const int ty = t >> 4;
    const int tx = t & 15;

    u64 acc2[4][8];
#pragma unroll
    for (int i = 0; i < 4; i++)
#pragma unroll
        for (int j = 0; j < 8; j++) acc2[i][j] = 0ULL;

    const int lrow = t >> 1;
    const int lcg  = t & 1;
    const int brow = t >> 5;
    const int bc   = (t & 31) * 4;

    for (int k0 = 0; k0 < 128; k0 += 8) {
        float4 av = make_float4(0.f, 0.f, 0.f, 0.f);
        int gr = m0 + lrow;
        if (gr < n) av = d_qg[(long long)gr * 64 + (k0 >> 2) + lcg];
        float4 bv4 = *(const float4*)(d_Wg + (k0 + brow) * 128 + bc);

        __syncthreads();
        As[lcg * 4 + 0][lrow] = av.x;
        As[lcg * 4 + 1][lrow] = av.y;
        As[lcg * 4 + 2][lrow] = av.z;
        As[lcg * 4 + 3][lrow] = av.w;
        *(float4*)&Bs[brow][bc] = bv4;
        __syncthreads();

#pragma unroll
        for (int kk = 0; kk < 8; kk++) {
            ulonglong2 a01 = *(const ulonglong2*)&As[kk][ty * 8];
            ulonglong2 a23 = *(const ulonglong2*)&As[kk][ty * 8 + 4];
            u64 ra2[4] = { a01.x, a01.y, a23.x, a23.y };

            float rb[8];
            *(float4*)(rb)     = *(float4*)&Bs[kk][tx * 8];
            *(float4*)(rb + 4) = *(float4*)&Bs[kk][tx * 8 + 4];
            u64 rbb[8];
#pragma unroll
            for (int j = 0; j < 8; j++) rbb[j] = bcast2(rb[j]);

#pragma unroll
            for (int i2 = 0; i2 < 4; i2++)
#pragma unroll
                for (int j = 0; j < 8; j++) fma2(acc2[i2][j], ra2[i2], rbb[j]);
        }
    }

    const int colf4 = tx * 2;
#pragma unroll
    for (int i2 = 0; i2 < 4; i2++) {
        float lo[8], hi[8];
#pragma unroll
        for (int j = 0; j < 8; j++) {
            float2 f = unpack2(acc2[i2][j]);
            lo[j] = f.x;
            hi[j] = f.y;
        }
#pragma unroll
        for (int half = 0; half < 2; half++) {
            int row = m0 + ty * 8 + 2 * i2 + half;
            if (row >= n) continue;
            const float* v = half ? hi : lo;
            long long r = row;
            d_qg[r * 64 + 32 + colf4]     = make_float4(v[0], v[1], v[2], v[3]);
            d_qg[r * 64 + 32 + colf4 + 1] = make_float4(v[4], v[5], v[6], v[7]);
        }
    }
}

// ---------------- K2: one warp per node, depth-2 prefetch, __ldcs ea gather ----------------
__global__ __launch_bounds__(256) void k2_nodes(const float* __restrict__ ea, int n)
{
    int node = (int)((blockIdx.x * 256u + threadIdx.x) >> 5);
    if (node >= n) return;
    const int lane = threadIdx.x & 31;
    const int li = lane & 15;

    const int start = d_off[node];
    const int end   = d_off[node + 1];

    const float4* qg = d_qg + (long long)node * 64;
    float4 q4 = qg[lane];
    float4 g4 = qg[32 + lane];

    float4 vac = make_float4(0.f, 0.f, 0.f, 0.f);
    float4 tac = make_float4(0.f, 0.f, 0.f, 0.f);
    float sw = 0.f;

    for (int j0 = start; j0 < end; j0 += 32) {
        int nb = end - j0; if (nb > 32) nb = 32;
        int2 se = (lane < nb) ? d_sed[j0 + lane] : make_int2(0, 0);

        // prefetch edge 0
        int src = __shfl_sync(0xffffffffu, se.x, 0);
        int eid = __shfl_sync(0xffffffffu, se.y, 0);
        const float4* kvp = d_kv + (long long)src * 64;
        float4 kc = kvp[lane];
        float4 vc = kvp[32 + lane];
        float4 ec = __ldcs(((const float4*)ea) + (long long)eid * 16 + li);

        for (int jj = 0; jj < nb; jj++) {
            int jn = (jj + 1 < nb) ? (jj + 1) : jj;
            int srcn = __shfl_sync(0xffffffffu, se.x, jn);
            int eidn = __shfl_sync(0xffffffffu, se.y, jn);
            const float4* kvn = d_kv + (long long)srcn * 64;
            float4 kn = kvn[lane];
            float4 vn = kvn[32 + lane];
            float4 en = __ldcs(((const float4*)ea) + (long long)eidn * 16 + li);

            float p = q4.x * kc.x + q4.y * kc.y + q4.z * kc.z + q4.w * kc.w
                    + ec.x * g4.x + ec.y * g4.y + ec.z * g4.z + ec.w * g4.w;

            p += __shfl_xor_sync(0xffffffffu, p, 8);
            p += __shfl_xor_sync(0xffffffffu, p, 4);
            p += __shfl_xor_sync(0xffffffffu, p, 2);
            p += __shfl_xor_sync(0xffffffffu, p, 1);

            float w = __expf(p * 0.125f);   // 1/sqrt(64)
            sw += w;
            vac.x += w * vc.x; vac.y += w * vc.y; vac.z += w * vc.z; vac.w += w * vc.w;
            tac.x += w * ec.x; tac.y += w * ec.y; tac.z += w * ec.z; tac.w += w * ec.w;

            kc = kn; vc = vn; ec = en;
        }
    }

    float inv = 1.f / (sw + 1e-16f);
    vac.x *= inv; vac.y *= inv; vac.z *= inv; vac.w *= inv;
    tac.x *= inv; tac.y *= inv; tac.z *= inv; tac.w *= inv;

    float4* accp = d_acc + (long long)node * 64;
    accp[lane]      = vac;
    accp[32 + lane] = tac;
}

// ---------------- K3: out += vaccN + taccN @ Wt  (GEMM) ----------------
__global__ __launch_bounds__(256) void k3_gemm(float* __restrict__ out, int n)
{
    __shared__ float As[8][128];
    __shared__ float Bs[8][128];

    const int t = threadIdx.x;
    const int m0 = blockIdx.x * 128;

    const int ty = t >> 4;
    const int tx = t & 15;

    u64 acc2[4][8];
#pragma unroll
    for (int i = 0; i < 4; i++)
#pragma unroll
        for (int j = 0; j < 8; j++) acc2[i][j] = 0ULL;

    const int lrow = t >> 1;
    const int lcg  = t & 1;
    const int brow = t >> 5;
    const int bc   = (t & 31) * 4;

    for (int k0 = 0; k0 < 128; k0 += 8) {
        float4 av = make_float4(0.f, 0.f, 0.f, 0.f);
        int gr = m0 + lrow;
        if (gr < n) av = d_acc[(long long)gr * 64 + 32 + (k0 >> 2) + lcg];
        float4 bv4 = *(const float4*)(d_Wt + (k0 + brow) * 128 + bc);

        __syncthreads();
        As[lcg * 4 + 0][lrow] = av.x;
        As[lcg * 4 + 1][lrow] = av.y;
        As[lcg * 4 + 2][lrow] = av.z;
        As[lcg * 4 + 3][lrow] = av.w;
        *(float4*)&Bs[brow][bc] = bv4;
        __syncthreads();

#pragma unroll
        for (int kk = 0; kk < 8; kk++) {
            ulonglong2 a01 = *(const ulonglong2*)&As[kk][ty * 8];
            ulonglong2 a23 = *(const ulonglong2*)&As[kk][ty * 8 + 4];
            u64 ra2[4] = { a01.x, a01.y, a23.x, a23.y };

            float rb[8];
            *(float4*)(rb)     = *(float4*)&Bs[kk][tx * 8];
            *(float4*)(rb + 4) = *(float4*)&Bs[kk][tx * 8 + 4];
            u64 rbb[8];
#pragma unroll
            for (int j = 0; j < 8; j++) rbb[j] = bcast2(rb[j]);

#pragma unroll
            for (int i2 = 0; i2 < 4; i2++)
#pragma unroll
                for (int j = 0; j < 8; j++) fma2(acc2[i2][j], ra2[i2], rbb[j]);
        }
    }

    const int colf4 = tx * 2;
#pragma unroll
    for (int i2 = 0; i2 < 4; i2++) {
        float lo[8], hi[8];
#pragma unroll
        for (int j = 0; j < 8; j++) {
            float2 f = unpack2(acc2[i2][j]);
            lo[j] = f.x;
            hi[j] = f.y;
        }
#pragma unroll
        for (int half = 0; half < 2; half++) {
            int row = m0 + ty * 8 + 2 * i2 + half;
            if (row >= n) continue;
            const float* v = half ? hi : lo;
            long long r = row;
            float4 va0 = d_acc[r * 64 + colf4];
            float4 va1 = d_acc[r * 64 + colf4 + 1];
            float4 o0 = ((float4*)out)[r * 32 + colf4];
            float4 o1 = ((float4*)out)[r * 32 + colf4 + 1];
            o0.x += va0.x + v[0]; o0.y += va0.y + v[1];
            o0.z += va0.z + v[2]; o0.w += va0.w + v[3];
            o1.x += va1.x + v[4]; o1.y += va1.y + v[5];
            o1.z += va1.z + v[6]; o1.w += va1.w + v[7];
            ((float4*)out)[r * 32 + colf4]     = o0;
            ((float4*)out)[r * 32 + colf4 + 1] = o1;
        }
    }
}

// ---------------- launch ----------------
extern "C" void kernel_launch(void* const* d_in, const int* in_sizes, int n_in,
                              void* d_out, int out_size)
{
    const float* x   = (const float*)d_in[0];
    const int*   ei  = (const int*)d_in[1];     // int32 (JAX x64 disabled)
    const float* ea  = (const float*)d_in[2];
    const float* Wq  = (const float*)d_in[3];
    const float* bq  = (const float*)d_in[4];
    const float* Wk  = (const float*)d_in[5];
    const float* bk  = (const float*)d_in[6];
    const float* Wv  = (const float*)d_in[7];
    const float* bv  = (const float*)d_in[8];
    const float* We  = (const float*)d_in[9];
    const float* Wsk = (const float*)d_in[10];
    const float* bsk = (const float*)d_in[11];

    int n = in_sizes[0] / INF;        // 50000
    int E = in_sizes[2] / ED;         // 1600000
    float* out = (float*)d_out;

    kWg<<<(HCC * HCC + 255) / 256, 256>>>(We);                          // launch 1

    dim3 g1((n + 127) / 128, 4);
    k1_gemm<<<g1, 256>>>(x, Wq, bq, Wk, bk, Wv, bv, Wsk, bsk, out, n);  // launch 2

    k0_zero<<<(NN + 255) / 256, 256>>>();                               // launch 3
    kg_gemm<<<(n + 127) / 128, 256>>>(n);                               // launch 4 (ncu slot)
    khist<<<1184, 256>>>(ei, E);                                        // launch 5
    kscan<<<1, 1024>>>();                                               // launch 6
    kscatter<<<1184, 256>>>(ei, E);                                     // launch 7
    kWt<<<(HCC * HCC + 255) / 256, 256>>>(We);                          // launch 8
    k2_nodes<<<(n * 32 + 255) / 256, 256>>>(ea, n);                     // launch 9
    k3_gemm<<<(n + 127) / 128, 256>>>(out, n);                          // launch 10
}